// round 9
// baseline (speedup 1.0000x reference)
#include <cuda_runtime.h>

// GlobalContextAttention — persistent CTA per segment, smem-staged j-pipeline.
// x (J, F, C=128) fp32, batch_index (F,) int32 SORTED, weight (C,C) fp32 -> out (J, B, C).
//
// R8 lesson: overlapping pass1/pass2 via L2 re-reads thrashes (126MB cap).
// Fix: hold the re-read slice in SMEM. One CTA per segment b (grid=128, one
// wave, 1024 thr, 1 CTA/SM, 217KB smem). Loop j: fused body streams slice j+1
// from DRAM into buffer N (accumulating its sum) while computing the gated
// pass of slice j from buffer C (smem; frames >CAP come from L2 at ~19MB reuse
// distance). DRAM stays busy through the whole kernel; x is read once.

static constexpr int C_DIM   = 128;
static constexpr int THREADS = 1024;
static constexpr int WARPS   = 32;
static constexpr int CAP     = 200;     // frames staged in smem per slice (100 KB)
static constexpr int MAX_SEG = 4096;
static constexpr int SMEM_BYTES = (2 * CAP * C_DIM + WARPS * C_DIM + C_DIM) * 4; // 221,696 B

__device__ int g_seg[MAX_SEG + 1];

__global__ void seg_bounds_kernel(const int* __restrict__ idx, int Fn, int Bn)
{
    const int t = blockIdx.x * blockDim.x + threadIdx.x;
    if (t > Bn) return;
    int lo = 0, hi = Fn;
    while (lo < hi) {
        int m = (lo + hi) >> 1;
        if (idx[m] < t) lo = m + 1; else hi = m;
    }
    g_seg[t] = lo;
}

__global__ __launch_bounds__(THREADS, 1)
void gca_fused_kernel(const float* __restrict__ x,
                      const float* __restrict__ W,
                      float*       __restrict__ out,
                      int Jn, int Fn, int Bn)
{
    extern __shared__ float dyn[];
    float* bufs  = dyn;                          // 2 x CAP x 128
    float* s_red = dyn + 2 * CAP * C_DIM;        // WARPS x 128 (reused: a2, a1, gemv)
    float* s_vec = s_red + WARPS * C_DIM;        // 128: mean, then gc

    const int tid  = threadIdx.x;
    const int warp = tid >> 5;
    const int lane = tid & 31;
    const int b    = blockIdx.x;

    const int start = g_seg[b];
    const int end   = g_seg[b + 1];
    const int cnt   = end - start;
    const int capn  = cnt < CAP ? cnt : CAP;
    const float inv_cnt = 1.0f / (float)(cnt > 0 ? cnt : 1);
    const int ch = lane * 4;
    const float* xbase = x + (size_t)start * C_DIM;   // + j*Fn*C per slice

    int cur = 0;   // buffer index holding slice j

    // ================= prologue: stage slice 0 + sum =================
    {
        const float* xj = xbase;                  // j = 0
        float* bw = bufs;                         // buffer 0
        float4 a1 = make_float4(0.f, 0.f, 0.f, 0.f);
        int f = warp;
        for (; f + 3 * WARPS < cnt; f += 4 * WARPS) {
#pragma unroll
            for (int u = 0; u < 4; u++) {
                const int fr = f + u * WARPS;
                const float4 v = *(const float4*)(xj + (size_t)fr * C_DIM + ch);
                if (fr < capn) *(float4*)(bw + fr * C_DIM + ch) = v;
                a1.x += v.x; a1.y += v.y; a1.z += v.z; a1.w += v.w;
            }
        }
        for (; f < cnt; f += WARPS) {
            const float4 v = *(const float4*)(xj + (size_t)f * C_DIM + ch);
            if (f < capn) *(float4*)(bw + f * C_DIM + ch) = v;
            a1.x += v.x; a1.y += v.y; a1.z += v.z; a1.w += v.w;
        }
        *(float4*)&s_red[warp * C_DIM + ch] = a1;
        __syncthreads();
        if (tid < C_DIM) {
            float s = 0.f;
#pragma unroll
            for (int w = 0; w < WARPS; w++) s += s_red[w * C_DIM + tid];
            s_vec[tid] = s * inv_cnt;             // mean[0,b,:]
        }
        __syncthreads();
        // gemv: 8-way k split (1024 thr): q = tid>>7 covers k in [q*16, q*16+16)
        {
            const int t_out = tid & (C_DIM - 1);
            const int q     = tid >> 7;
            const float* wp = W + (size_t)(q * 16) * C_DIM + t_out;
            float p = 0.f;
#pragma unroll
            for (int k = 0; k < 16; k++)
                p += s_vec[q * 16 + k] * wp[(size_t)k * C_DIM];
            __syncthreads();                      // s_vec read done before overwrite below
            s_red[q * C_DIM + t_out] = p;
        }
        __syncthreads();
        if (tid < C_DIM) {
            float g = 0.f;
#pragma unroll
            for (int q = 0; q < 8; q++) g += s_red[q * C_DIM + tid];
            s_vec[tid] = tanhf(g);                // gc[0,b,:]
        }
        __syncthreads();
    }

    // ================= main loop: pass2(j) fused with stage(j+1) =================
    for (int j = 0; j < Jn; j++) {
        const bool have_next = (j + 1 < Jn);
        const float* xp = xbase + (size_t)j * Fn * C_DIM;          // overflow L2 reads
        const float* xn = xbase + (size_t)(j + 1) * Fn * C_DIM;    // next-slice DRAM stream
        const float* bc = bufs + cur * CAP * C_DIM;                // staged slice j
        float*       bn = bufs + (1 - cur) * CAP * C_DIM;          // target for slice j+1
        const float4 gc4 = *(const float4*)&s_vec[ch];

        float4 a1 = make_float4(0.f, 0.f, 0.f, 0.f);
        float4 a2 = make_float4(0.f, 0.f, 0.f, 0.f);
        int f = warp;
        for (; f + WARPS < cnt; f += 2 * WARPS) {
            const int f0 = f, f1 = f + WARPS;
            // issue all loads first (DRAM stream + pass2 source)
            float4 n0, n1;
            if (have_next) {
                n0 = *(const float4*)(xn + (size_t)f0 * C_DIM + ch);
                n1 = *(const float4*)(xn + (size_t)f1 * C_DIM + ch);
            }
            const float4 o0 = (f0 < capn) ? *(const float4*)(bc + f0 * C_DIM + ch)
                                          : *(const float4*)(xp + (size_t)f0 * C_DIM + ch);
            const float4 o1 = (f1 < capn) ? *(const float4*)(bc + f1 * C_DIM + ch)
                                          : *(const float4*)(xp + (size_t)f1 * C_DIM + ch);
            if (have_next) {
                if (f0 < capn) *(float4*)(bn + f0 * C_DIM + ch) = n0;
                if (f1 < capn) *(float4*)(bn + f1 * C_DIM + ch) = n1;
                a1.x += n0.x + n1.x; a1.y += n0.y + n1.y;
                a1.z += n0.z + n1.z; a1.w += n0.w + n1.w;
            }
            float d0 = o0.x*gc4.x + o0.y*gc4.y + o0.z*gc4.z + o0.w*gc4.w;
            float d1 = o1.x*gc4.x + o1.y*gc4.y + o1.z*gc4.z + o1.w*gc4.w;
#pragma unroll
            for (int s = 16; s > 0; s >>= 1) {
                d0 += __shfl_xor_sync(0xffffffffu, d0, s);
                d1 += __shfl_xor_sync(0xffffffffu, d1, s);
            }
            const float g0 = 1.f / (1.f + __expf(-d0));
            const float g1 = 1.f / (1.f + __expf(-d1));
            a2.x += g0*o0.x + g1*o1.x; a2.y += g0*o0.y + g1*o1.y;
            a2.z += g0*o0.z + g1*o1.z; a2.w += g0*o0.w + g1*o1.w;
        }
        for (; f < cnt; f += WARPS) {
            float4 n0;
            if (have_next) n0 = *(const float4*)(xn + (size_t)f * C_DIM + ch);
            const float4 o0 = (f < capn) ? *(const float4*)(bc + f * C_DIM + ch)
                                         : *(const float4*)(xp + (size_t)f * C_DIM + ch);
            if (have_next) {
                if (f < capn) *(float4*)(bn + f * C_DIM + ch) = n0;
                a1.x += n0.x; a1.y += n0.y; a1.z += n0.z; a1.w += n0.w;
            }
            float d = o0.x*gc4.x + o0.y*gc4.y + o0.z*gc4.z + o0.w*gc4.w;
#pragma unroll
            for (int s = 16; s > 0; s >>= 1)
                d += __shfl_xor_sync(0xffffffffu, d, s);
            const float g = 1.f / (1.f + __expf(-d));
            a2.x += g*o0.x; a2.y += g*o0.y; a2.z += g*o0.z; a2.w += g*o0.w;
        }

        // ---- reduce a2 -> out(j) ----
        __syncthreads();
        *(float4*)&s_red[warp * C_DIM + ch] = a2;
        __syncthreads();
        if (tid < C_DIM) {
            float s = 0.f;
#pragma unroll
            for (int w = 0; w < WARPS; w++) s += s_red[w * C_DIM + tid];
            out[((size_t)j * Bn + b) * C_DIM + tid] = s * inv_cnt;
        }

        if (have_next) {
            // ---- reduce a1 -> mean(j+1) -> gemv -> gc ----
            __syncthreads();
            *(float4*)&s_red[warp * C_DIM + ch] = a1;
            __syncthreads();
            if (tid < C_DIM) {
                float s = 0.f;
#pragma unroll
                for (int w = 0; w < WARPS; w++) s += s_red[w * C_DIM + tid];
                s_vec[tid] = s * inv_cnt;
            }
            __syncthreads();
            {
                const int t_out = tid & (C_DIM - 1);
                const int q     = tid >> 7;
                const float* wp = W + (size_t)(q * 16) * C_DIM + t_out;
                float p = 0.f;
#pragma unroll
                for (int k = 0; k < 16; k++)
                    p += s_vec[q * 16 + k] * wp[(size_t)k * C_DIM];
                __syncthreads();
                s_red[q * C_DIM + t_out] = p;
            }
            __syncthreads();
            if (tid < C_DIM) {
                float g = 0.f;
#pragma unroll
                for (int q = 0; q < 8; q++) g += s_red[q * C_DIM + tid];
                s_vec[tid] = tanhf(g);            // gc[j+1,b,:]
            }
            __syncthreads();
        }
        cur = 1 - cur;
    }
}

extern "C" void kernel_launch(void* const* d_in, const int* in_sizes, int n_in,
                              void* d_out, int out_size)
{
    // Identify inputs by element count: x = largest; weight = C*C; idx = other multi-element.
    int xi = 0;
    for (int i = 1; i < n_in; i++)
        if (in_sizes[i] > in_sizes[xi]) xi = i;
    int wi = -1, ii = -1;
    for (int i = 0; i < n_in; i++) {
        if (i == xi) continue;
        if (in_sizes[i] == C_DIM * C_DIM && wi < 0) { wi = i; continue; }
        if (in_sizes[i] > 1 && ii < 0) ii = i;
    }
    if (wi < 0 || ii < 0) return;

    const float* x   = (const float*)d_in[xi];
    const int*   idx = (const int*)  d_in[ii];
    const float* W   = (const float*)d_in[wi];
    float*       out = (float*)d_out;

    const int Fn = in_sizes[ii];
    const int Jn = in_sizes[xi] / (Fn * C_DIM);
    int Bn = out_size / (Jn * C_DIM);
    if (Bn > MAX_SEG) Bn = MAX_SEG;

    static bool attr_set = false;
    if (!attr_set) {
        cudaFuncSetAttribute(gca_fused_kernel,
                             cudaFuncAttributeMaxDynamicSharedMemorySize, SMEM_BYTES);
        attr_set = true;
    }

    seg_bounds_kernel<<<(Bn + 255) / 256 + 1, 256>>>(idx, Fn, Bn);
    gca_fused_kernel<<<Bn, THREADS, SMEM_BYTES>>>(x, W, out, Jn, Fn, Bn);
}

// round 10
// speedup vs baseline: 1.5205x; 1.5205x over previous
#include <cuda_runtime.h>

// GlobalContextAttention — j-pipelined fusion v2: overlap DRAM pass with L2 pass,
// live set held well under the L2 cap.
// x (J, F, C=128) fp32, batch_index (F,) int32 SORTED, weight (C,C) fp32 -> out (J, B, C).
//
// R8 proved the overlap raises DRAM busy (62.8%) but its 115MB live set thrashed
// L2 (850MB traffic). R10: grid = B x 2 = 256 CTAs -> live set 256 x 2 slices
// ~ 77MB << 126MB; 512-thread CTAs at 2/SM -> 32 warps/SM; fused body issues
// 3 DRAM + 3 L2 loads up front per iteration. x should be read ~once again
// while DRAM stays busy through pass2 windows.

static constexpr int C_DIM   = 128;
static constexpr int THREADS = 512;
static constexpr int WARPS   = 16;
static constexpr int G_SPLIT = 2;
static constexpr int MAX_SEG = 4096;

__device__ int g_seg[MAX_SEG + 1];

__global__ void seg_bounds_kernel(const int* __restrict__ idx, int Fn, int Bn)
{
    const int t = blockIdx.x * blockDim.x + threadIdx.x;
    if (t > Bn) return;
    int lo = 0, hi = Fn;
    while (lo < hi) {
        int m = (lo + hi) >> 1;
        if (idx[m] < t) lo = m + 1; else hi = m;
    }
    g_seg[t] = lo;
}

__device__ __forceinline__ float warp_gate(float d) {
#pragma unroll
    for (int s = 16; s > 0; s >>= 1)
        d += __shfl_xor_sync(0xffffffffu, d, s);
    return 1.f / (1.f + __expf(-d));
}

__global__ __launch_bounds__(THREADS, 2)
void gca_fused_kernel(const float* __restrict__ x,
                      const float* __restrict__ W,
                      float*       __restrict__ out,
                      int Jn, int Fn, int Bn)
{
    __shared__ float s_p1[WARPS * C_DIM];   // pass1 partials (also gemv partials)
    __shared__ float s_p2[WARPS * C_DIM];   // pass2 partials
    __shared__ float s_vec[C_DIM];          // mean, then gc

    const int tid  = threadIdx.x;
    const int warp = tid >> 5;
    const int lane = tid & 31;
    const int b    = blockIdx.x;
    const int g    = blockIdx.y;

    const int jb = (g * Jn) / G_SPLIT;
    const int je = ((g + 1) * Jn) / G_SPLIT;
    if (jb >= je) return;

    const int start = g_seg[b];
    const int end   = g_seg[b + 1];
    const int cnt   = end - start;
    const float inv_cnt = 1.0f / (float)(cnt > 0 ? cnt : 1);
    const int ch = lane * 4;

    // ================= prologue: pass1 for j = jb (unroll 6) =================
    {
        const float* xj = x + (size_t)jb * Fn * C_DIM;
        float4 acc = make_float4(0.f, 0.f, 0.f, 0.f);
        int f = start + warp;
        for (; f + 5 * WARPS < end; f += 6 * WARPS) {
#pragma unroll
            for (int u = 0; u < 6; u++) {
                const float4 a = *(const float4*)(xj + (size_t)(f + u * WARPS) * C_DIM + ch);
                acc.x += a.x; acc.y += a.y; acc.z += a.z; acc.w += a.w;
            }
        }
        for (; f < end; f += WARPS) {
            const float4 a = *(const float4*)(xj + (size_t)f * C_DIM + ch);
            acc.x += a.x; acc.y += a.y; acc.z += a.z; acc.w += a.w;
        }
        *(float4*)&s_p1[warp * C_DIM + ch] = acc;
    }
    __syncthreads();
    if (tid < C_DIM) {
        float s = 0.f;
#pragma unroll
        for (int w = 0; w < WARPS; w++) s += s_p1[w * C_DIM + tid];
        s_vec[tid] = s * inv_cnt;           // mean[jb,b,:]
    }
    __syncthreads();
    // gemv gc = tanh(mean @ W): 512 threads, k split into 4 quarters of 32
    {
        const int t_out = tid & (C_DIM - 1);
        const int q     = tid >> 7;         // 0..3
        const float* wp = W + (size_t)(q * 32) * C_DIM + t_out;
        float p = 0.f;
#pragma unroll 8
        for (int k = 0; k < 32; k++)
            p += s_vec[q * 32 + k] * wp[(size_t)k * C_DIM];
        s_p1[q * C_DIM + t_out] = p;
    }
    __syncthreads();
    if (tid < C_DIM)
        s_vec[tid] = tanhf(s_p1[tid] + s_p1[C_DIM + tid] +
                           s_p1[2 * C_DIM + tid] + s_p1[3 * C_DIM + tid]);
    __syncthreads();

    // ================= steady state: pass1(j) fused with pass2(j-1) ==========
    for (int j = jb + 1; j < je; j++) {
        const float* xc = x + (size_t)j       * Fn * C_DIM;  // current (DRAM stream)
        const float* xp = x + (size_t)(j - 1) * Fn * C_DIM;  // previous (L2-hot)
        const float4 gc4 = *(const float4*)&s_vec[ch];

        float4 a1 = make_float4(0.f, 0.f, 0.f, 0.f);   // pass1 acc
        float4 a2 = make_float4(0.f, 0.f, 0.f, 0.f);   // pass2 acc
        int f = start + warp;
        for (; f + 2 * WARPS < end; f += 3 * WARPS) {
            // issue all 6 loads up front (3 DRAM + 3 L2 in flight)
            const float4 n0 = *(const float4*)(xc + (size_t)(f            ) * C_DIM + ch);
            const float4 n1 = *(const float4*)(xc + (size_t)(f +     WARPS) * C_DIM + ch);
            const float4 n2 = *(const float4*)(xc + (size_t)(f + 2 * WARPS) * C_DIM + ch);
            const float4 o0 = *(const float4*)(xp + (size_t)(f            ) * C_DIM + ch);
            const float4 o1 = *(const float4*)(xp + (size_t)(f +     WARPS) * C_DIM + ch);
            const float4 o2 = *(const float4*)(xp + (size_t)(f + 2 * WARPS) * C_DIM + ch);
            a1.x += n0.x + n1.x + n2.x; a1.y += n0.y + n1.y + n2.y;
            a1.z += n0.z + n1.z + n2.z; a1.w += n0.w + n1.w + n2.w;
            float d0 = o0.x*gc4.x + o0.y*gc4.y + o0.z*gc4.z + o0.w*gc4.w;
            float d1 = o1.x*gc4.x + o1.y*gc4.y + o1.z*gc4.z + o1.w*gc4.w;
            float d2 = o2.x*gc4.x + o2.y*gc4.y + o2.z*gc4.z + o2.w*gc4.w;
#pragma unroll
            for (int s = 16; s > 0; s >>= 1) {
                d0 += __shfl_xor_sync(0xffffffffu, d0, s);
                d1 += __shfl_xor_sync(0xffffffffu, d1, s);
                d2 += __shfl_xor_sync(0xffffffffu, d2, s);
            }
            const float g0 = 1.f / (1.f + __expf(-d0));
            const float g1 = 1.f / (1.f + __expf(-d1));
            const float g2 = 1.f / (1.f + __expf(-d2));
            a2.x += g0*o0.x + g1*o1.x + g2*o2.x;
            a2.y += g0*o0.y + g1*o1.y + g2*o2.y;
            a2.z += g0*o0.z + g1*o1.z + g2*o2.z;
            a2.w += g0*o0.w + g1*o1.w + g2*o2.w;
        }
        for (; f < end; f += WARPS) {
            const float4 n0 = *(const float4*)(xc + (size_t)f * C_DIM + ch);
            const float4 o0 = *(const float4*)(xp + (size_t)f * C_DIM + ch);
            a1.x += n0.x; a1.y += n0.y; a1.z += n0.z; a1.w += n0.w;
            const float g0 = warp_gate(o0.x*gc4.x + o0.y*gc4.y + o0.z*gc4.z + o0.w*gc4.w);
            a2.x += g0*o0.x; a2.y += g0*o0.y; a2.z += g0*o0.z; a2.w += g0*o0.w;
        }
        *(float4*)&s_p1[warp * C_DIM + ch] = a1;
        *(float4*)&s_p2[warp * C_DIM + ch] = a2;
        __syncthreads();
        if (tid < C_DIM) {
            float s2 = 0.f, s1 = 0.f;
#pragma unroll
            for (int w = 0; w < WARPS; w++) {
                s2 += s_p2[w * C_DIM + tid];
                s1 += s_p1[w * C_DIM + tid];
            }
            out[((size_t)(j - 1) * Bn + b) * C_DIM + tid] = s2 * inv_cnt;
            s_vec[tid] = s1 * inv_cnt;       // mean[j,b,:]
        }
        __syncthreads();
        {
            const int t_out = tid & (C_DIM - 1);
            const int q     = tid >> 7;
            const float* wp = W + (size_t)(q * 32) * C_DIM + t_out;
            float p = 0.f;
#pragma unroll 8
            for (int k = 0; k < 32; k++)
                p += s_vec[q * 32 + k] * wp[(size_t)k * C_DIM];
            __syncthreads();                  // mean reads done before overwrite
            s_p1[q * C_DIM + t_out] = p;
        }
        __syncthreads();
        if (tid < C_DIM)
            s_vec[tid] = tanhf(s_p1[tid] + s_p1[C_DIM + tid] +
                               s_p1[2 * C_DIM + tid] + s_p1[3 * C_DIM + tid]);
        __syncthreads();
    }

    // ================= drain: pass2 for j = je-1 (unroll 4) =========
    {
        const float* xp = x + (size_t)(je - 1) * Fn * C_DIM;
        const float4 gc4 = *(const float4*)&s_vec[ch];
        float4 a2 = make_float4(0.f, 0.f, 0.f, 0.f);
        int f = start + warp;
        for (; f + 3 * WARPS < end; f += 4 * WARPS) {
            float4 o[4];
#pragma unroll
            for (int u = 0; u < 4; u++)
                o[u] = *(const float4*)(xp + (size_t)(f + u * WARPS) * C_DIM + ch);
            float d[4];
#pragma unroll
            for (int u = 0; u < 4; u++)
                d[u] = o[u].x*gc4.x + o[u].y*gc4.y + o[u].z*gc4.z + o[u].w*gc4.w;
#pragma unroll
            for (int s = 16; s > 0; s >>= 1) {
#pragma unroll
                for (int u = 0; u < 4; u++)
                    d[u] += __shfl_xor_sync(0xffffffffu, d[u], s);
            }
#pragma unroll
            for (int u = 0; u < 4; u++) {
                const float gg = 1.f / (1.f + __expf(-d[u]));
                a2.x += gg*o[u].x; a2.y += gg*o[u].y; a2.z += gg*o[u].z; a2.w += gg*o[u].w;
            }
        }
        for (; f < end; f += WARPS) {
            const float4 o0 = *(const float4*)(xp + (size_t)f * C_DIM + ch);
            const float gg = warp_gate(o0.x*gc4.x + o0.y*gc4.y + o0.z*gc4.z + o0.w*gc4.w);
            a2.x += gg*o0.x; a2.y += gg*o0.y; a2.z += gg*o0.z; a2.w += gg*o0.w;
        }
        *(float4*)&s_p2[warp * C_DIM + ch] = a2;
        __syncthreads();
        if (tid < C_DIM) {
            float s = 0.f;
#pragma unroll
            for (int w = 0; w < WARPS; w++) s += s_p2[w * C_DIM + tid];
            out[((size_t)(je - 1) * Bn + b) * C_DIM + tid] = s * inv_cnt;
        }
    }
}

extern "C" void kernel_launch(void* const* d_in, const int* in_sizes, int n_in,
                              void* d_out, int out_size)
{
    // Identify inputs by element count: x = largest; weight = C*C; idx = other multi-element.
    int xi = 0;
    for (int i = 1; i < n_in; i++)
        if (in_sizes[i] > in_sizes[xi]) xi = i;
    int wi = -1, ii = -1;
    for (int i = 0; i < n_in; i++) {
        if (i == xi) continue;
        if (in_sizes[i] == C_DIM * C_DIM && wi < 0) { wi = i; continue; }
        if (in_sizes[i] > 1 && ii < 0) ii = i;
    }
    if (wi < 0 || ii < 0) return;

    const float* x   = (const float*)d_in[xi];
    const int*   idx = (const int*)  d_in[ii];
    const float* W   = (const float*)d_in[wi];
    float*       out = (float*)d_out;

    const int Fn = in_sizes[ii];
    const int Jn = in_sizes[xi] / (Fn * C_DIM);
    int Bn = out_size / (Jn * C_DIM);
    if (Bn > MAX_SEG) Bn = MAX_SEG;

    seg_bounds_kernel<<<(Bn + 255) / 256 + 1, 256>>>(idx, Fn, Bn);
    dim3 grid(Bn, G_SPLIT);
    gca_fused_kernel<<<grid, THREADS>>>(x, W, out, Jn, Fn, Bn);
}